// round 2
// baseline (speedup 1.0000x reference)
#include <cuda_runtime.h>
#include <math.h>

// J2 plane-strain elastoplasticity PRNN, fused full-sequence kernel.
// One thread = one material point; T-loop in registers; 16-lane shfl
// reduction for the fc2 output per batch element.

namespace {
constexpr double E_MOD_D = 3130.0;
constexpr double NU_D    = 0.37;
constexpr double SIG_Y_D = 64.8;
constexpr double H_ISO_D = 300.0;
constexpr double MU_D    = E_MOD_D / (2.0 * (1.0 + NU_D));
constexpr double LAM_D   = E_MOD_D * NU_D / ((1.0 + NU_D) * (1.0 - 2.0 * NU_D));

constexpr int T_STEPS = 128;
constexpr int F_DIM   = 3;
constexpr int MATPTS  = 16;
constexpr int L_DIM   = MATPTS * F_DIM;   // 48
constexpr int O_DIM   = 3;
}

__global__ __launch_bounds__(256)
void prnn_j2_kernel(const float* __restrict__ x,
                    const float* __restrict__ W1,
                    const float* __restrict__ W2,
                    float* __restrict__ out,
                    int n_batch)
{
    const float MU    = (float)MU_D;
    const float LAM   = (float)LAM_D;
    const float SIG_Y = (float)SIG_Y_D;
    const float H_ISO = (float)H_ISO_D;
    const float INV_3MU_H = (float)(1.0 / (3.0 * MU_D + H_ISO_D));
    const float TWO_MU = 2.0f * MU;

    const int tid = blockIdx.x * blockDim.x + threadIdx.x;
    const int b = tid >> 4;        // batch element
    const int m = tid & 15;        // material point within batch element
    if (b >= n_batch) return;

    // fc1 rows for this material point's 3 strain components: W1[3m+i, j]
    float w1[3][3];
#pragma unroll
    for (int i = 0; i < 3; i++)
#pragma unroll
        for (int j = 0; j < 3; j++)
            w1[i][j] = W1[(3 * m + i) * F_DIM + j];

    // softplus(W2) columns for this material point: W2s[o, 3m+i]
    float w2s[3][3];
#pragma unroll
    for (int o = 0; o < 3; o++)
#pragma unroll
        for (int i = 0; i < 3; i++) {
            float w = W2[o * L_DIM + 3 * m + i];
            // numerically stable softplus: max(w,0) + log1p(exp(-|w|))
            w2s[o][i] = fmaxf(w, 0.0f) + log1pf(expf(-fabsf(w)));
        }

    // committed history state (registers)
    float pxx = 0.0f, pyy = 0.0f, pzz = 0.0f, pxy = 0.0f, alpha = 0.0f;

    const float* xb = x   + (size_t)b * T_STEPS * F_DIM;
    float*       ob = out + (size_t)b * T_STEPS * O_DIM;
    const bool leader = (m == 0);

#pragma unroll 2
    for (int t = 0; t < T_STEPS; t++) {
        const float x0 = __ldg(xb + t * 3 + 0);
        const float x1 = __ldg(xb + t * 3 + 1);
        const float x2 = __ldg(xb + t * 3 + 2);

        // fc1: strain components for this material point
        const float exx = w1[0][0] * x0 + w1[0][1] * x1 + w1[0][2] * x2;
        const float eyy = w1[1][0] * x0 + w1[1][1] * x1 + w1[1][2] * x2;
        const float gxy = w1[2][0] * x0 + w1[2][1] * x1 + w1[2][2] * x2;

        // elastic predictor
        const float ee_xx = exx - pxx;
        const float ee_yy = eyy - pyy;
        const float ee_zz = -pzz;
        const float ee_xy = 0.5f * gxy - pxy;
        const float tr = ee_xx + ee_yy + ee_zz;
        const float ltr = LAM * tr;
        const float sxx = ltr + TWO_MU * ee_xx;
        const float syy = ltr + TWO_MU * ee_yy;
        const float szz = ltr + TWO_MU * ee_zz;
        const float sxy = TWO_MU * ee_xy;

        const float pm = (sxx + syy + szz) * (1.0f / 3.0f);
        const float dxx = sxx - pm;
        const float dyy = syy - pm;
        const float dzz = szz - pm;
        const float q2 = 1.5f * (dxx * dxx + dyy * dyy + dzz * dzz
                                 + 2.0f * sxy * sxy);
        const float q = sqrtf(q2);

        // radial return (closed form, linear isotropic hardening)
        const float fyield = q - (SIG_Y + H_ISO * alpha);
        const float dgam = fmaxf(fyield, 0.0f) * INV_3MU_H;
        const float qs = fmaxf(q, 1e-12f);
        const float r = 1.5f / qs;
        const float nxx = dxx * r;
        const float nyy = dyy * r;
        const float nzz = dzz * r;
        const float nxy = sxy * r;
        const float tmd = TWO_MU * dgam;

        const float oxx = sxx - tmd * nxx;
        const float oyy = syy - tmd * nyy;
        const float oxy = sxy - tmd * nxy;

        // commit history
        pxx += dgam * nxx;
        pyy += dgam * nyy;
        pzz += dgam * nzz;
        pxy += dgam * nxy;
        alpha += dgam;

        // fc2 partial (this material point's 3 stress components)
        float y0 = w2s[0][0] * oxx + w2s[0][1] * oyy + w2s[0][2] * oxy;
        float y1 = w2s[1][0] * oxx + w2s[1][1] * oyy + w2s[1][2] * oxy;
        float y2 = w2s[2][0] * oxx + w2s[2][1] * oyy + w2s[2][2] * oxy;

        // reduce across the 16 material points of this batch element
#pragma unroll
        for (int off = 8; off >= 1; off >>= 1) {
            y0 += __shfl_xor_sync(0xffffffffu, y0, off);
            y1 += __shfl_xor_sync(0xffffffffu, y1, off);
            y2 += __shfl_xor_sync(0xffffffffu, y2, off);
        }
        if (leader) {
            ob[t * 3 + 0] = y0;
            ob[t * 3 + 1] = y1;
            ob[t * 3 + 2] = y2;
        }
    }
}

extern "C" void kernel_launch(void* const* d_in, const int* in_sizes, int n_in,
                              void* d_out, int out_size)
{
    const float* x  = (const float*)d_in[0];   // [B, 128, 3]
    const float* W1 = (const float*)d_in[1];   // [48, 3]
    const float* W2 = (const float*)d_in[2];   // [3, 48]
    float* out = (float*)d_out;                // [B, 128, 3]

    const int n_batch = in_sizes[0] / (T_STEPS * F_DIM);   // 16384
    const int n_points = n_batch * MATPTS;                  // 262144
    const int threads = 256;
    const int blocks = (n_points + threads - 1) / threads;

    prnn_j2_kernel<<<blocks, threads>>>(x, W1, W2, out, n_batch);
}

// round 4
// speedup vs baseline: 1.3921x; 1.3921x over previous
#include <cuda_runtime.h>
#include <math.h>

// J2 plane-strain elastoplasticity PRNN, fused full-sequence kernel, v2b.
// 2 material points per thread via packed f32x2 math (FFMA2);
// 8-lane shfl butterfly output reduction; negative-plastic-strain
// refactor removes all subtractions and the explicit flow normals.

namespace {
constexpr double E_MOD_D = 3130.0;
constexpr double NU_D    = 0.37;
constexpr double SIG_Y_D = 64.8;
constexpr double H_ISO_D = 300.0;
constexpr double MU_D    = E_MOD_D / (2.0 * (1.0 + NU_D));
constexpr double LAM_D   = E_MOD_D * NU_D / ((1.0 + NU_D) * (1.0 - 2.0 * NU_D));

constexpr int T_STEPS = 128;
constexpr int F_DIM   = 3;
constexpr int MATPTS  = 16;
constexpr int L_DIM   = MATPTS * F_DIM;   // 48
}

// ---- packed f32x2 helpers (sm_103a) ----
typedef unsigned long long f2t;

__device__ __forceinline__ f2t f2pack(float lo, float hi) {
    f2t r;
    asm("mov.b64 %0, {%1, %2};" : "=l"(r) : "f"(lo), "f"(hi));
    return r;
}
__device__ __forceinline__ void f2unpack(f2t a, float& lo, float& hi) {
    asm("mov.b64 {%0, %1}, %2;" : "=f"(lo), "=f"(hi) : "l"(a));
}
__device__ __forceinline__ f2t f2fma(f2t a, f2t b, f2t c) {
    f2t d;
    asm("fma.rn.f32x2 %0, %1, %2, %3;" : "=l"(d) : "l"(a), "l"(b), "l"(c));
    return d;
}
__device__ __forceinline__ f2t f2mul(f2t a, f2t b) {
    f2t d;
    asm("mul.rn.f32x2 %0, %1, %2;" : "=l"(d) : "l"(a), "l"(b));
    return d;
}
__device__ __forceinline__ f2t f2add(f2t a, f2t b) {
    f2t d;
    asm("add.rn.f32x2 %0, %1, %2;" : "=l"(d) : "l"(a), "l"(b));
    return d;
}

__global__ __launch_bounds__(256)
void prnn_j2_kernel2(const float* __restrict__ x,
                     const float* __restrict__ W1,
                     const float* __restrict__ W2,
                     float* __restrict__ out,
                     int n_batch)
{
    const float MU    = (float)MU_D;
    const float LAM   = (float)LAM_D;
    const float SIG_Y = (float)SIG_Y_D;
    const float H_ISO = (float)H_ISO_D;
    const float INV_3MU_H   = (float)(1.0 / (3.0 * MU_D + H_ISO_D));
    const float NEG15_INV   = -1.5f * INV_3MU_H;   // folds -1.5/(3MU+H)
    const float TWO_MU = 2.0f * MU;

    const int tid = blockIdx.x * blockDim.x + threadIdx.x;
    const int b  = tid >> 3;         // batch element (8 threads per element)
    const int l8 = tid & 7;          // lane within 8-lane group
    if (b >= n_batch) return;

    const int m0 = l8;               // material point (lo half)
    const int m1 = l8 + 8;           // material point (hi half)

    // fc1 rows, packed across the two points; shear row pre-scaled by 0.5
    f2t w1p[3][3];
#pragma unroll
    for (int i = 0; i < 3; i++) {
        const float s = (i == 2) ? 0.5f : 1.0f;
#pragma unroll
        for (int j = 0; j < 3; j++)
            w1p[i][j] = f2pack(s * W1[(3 * m0 + i) * F_DIM + j],
                               s * W1[(3 * m1 + i) * F_DIM + j]);
    }

    // softplus(W2) entries for the two points, packed
    f2t w2p[3][3];
#pragma unroll
    for (int o = 0; o < 3; o++)
#pragma unroll
        for (int i = 0; i < 3; i++) {
            const float a = W2[o * L_DIM + 3 * m0 + i];
            const float c = W2[o * L_DIM + 3 * m1 + i];
            const float sa = fmaxf(a, 0.0f) + log1pf(expf(-fabsf(a)));
            const float sc = fmaxf(c, 0.0f) + log1pf(expf(-fabsf(c)));
            w2p[o][i] = f2pack(sa, sc);
        }

    // packed constants
    const f2t LAMp  = f2pack(LAM, LAM);
    const f2t TMUp  = f2pack(TWO_MU, TWO_MU);
    const f2t M13p  = f2pack(-1.0f / 3.0f, -1.0f / 3.0f);
    const f2t C15p  = f2pack(1.5f, 1.5f);
    const f2t ZEROp = f2pack(0.0f, 0.0f);

    // committed history: NEGATIVE plastic strain (packed) + alpha (scalar halves)
    f2t npxx = ZEROp, npyy = ZEROp, npzz = ZEROp, npxy = ZEROp;
    float alpha0 = 0.0f, alpha1 = 0.0f;

    const float* xb = x   + (size_t)b * T_STEPS * 3;
    float*       ob = out + (size_t)b * T_STEPS * 3;
    const bool leader = (l8 == 0);

#pragma unroll 2
    for (int t = 0; t < T_STEPS; t++) {
        const float xa = __ldg(xb + t * 3 + 0);
        const float xbv = __ldg(xb + t * 3 + 1);
        const float xc = __ldg(xb + t * 3 + 2);
        const f2t xp0 = f2pack(xa, xa);
        const f2t xp1 = f2pack(xbv, xbv);
        const f2t xp2 = f2pack(xc, xc);

        // elastic strain = fc1(x) + negative plastic strain (pure FMA chains)
        const f2t ee_xx = f2fma(w1p[0][0], xp0, f2fma(w1p[0][1], xp1, f2fma(w1p[0][2], xp2, npxx)));
        const f2t ee_yy = f2fma(w1p[1][0], xp0, f2fma(w1p[1][1], xp1, f2fma(w1p[1][2], xp2, npyy)));
        const f2t ee_xy = f2fma(w1p[2][0], xp0, f2fma(w1p[2][1], xp1, f2fma(w1p[2][2], xp2, npxy)));
        const f2t ee_zz = npzz;

        // trial stress
        const f2t tr  = f2add(f2add(ee_xx, ee_yy), ee_zz);
        const f2t ltr = f2mul(LAMp, tr);
        const f2t sxx = f2fma(TMUp, ee_xx, ltr);
        const f2t syy = f2fma(TMUp, ee_yy, ltr);
        const f2t szz = f2fma(TMUp, ee_zz, ltr);
        const f2t sxy = f2mul(TMUp, ee_xy);

        // deviator via negative mean pressure
        const f2t pmn = f2mul(f2add(f2add(sxx, syy), szz), M13p);
        const f2t dxx = f2add(sxx, pmn);
        const f2t dyy = f2add(syy, pmn);
        const f2t dzz = f2add(szz, pmn);

        // q^2 = 1.5*(dxx^2+dyy^2+dzz^2+2*sxy^2)
        const f2t t2  = f2mul(sxy, sxy);
        const f2t q2p = f2mul(C15p,
                        f2fma(dxx, dxx, f2fma(dyy, dyy, f2fma(dzz, dzz, f2add(t2, t2)))));

        // scalar radial-return per half: rq = 1/q, cneg = -1.5*dgam/q
        float q2a, q2b;
        f2unpack(q2p, q2a, q2b);

        const float rq0 = rsqrtf(fmaxf(q2a, 1e-24f));
        const float rq1 = rsqrtf(fmaxf(q2b, 1e-24f));
        const float qv0 = q2a * rq0;
        const float qv1 = q2b * rq1;
        const float f0 = qv0 - fmaf(H_ISO, alpha0, SIG_Y);
        const float f1 = qv1 - fmaf(H_ISO, alpha1, SIG_Y);
        const float g0 = fmaxf(f0, 0.0f);
        const float g1 = fmaxf(f1, 0.0f);
        alpha0 = fmaf(g0, INV_3MU_H, alpha0);
        alpha1 = fmaf(g1, INV_3MU_H, alpha1);
        const float cn0 = (g0 * NEG15_INV) * rq0;
        const float cn1 = (g1 * NEG15_INV) * rq1;

        const f2t cpk = f2pack(cn0, cn1);       // -dgam*1.5/q
        const f2t spk = f2mul(cpk, TMUp);       // -2*MU*dgam*1.5/q

        // corrected stress (radial return)
        const f2t oxx = f2fma(spk, dxx, sxx);
        const f2t oyy = f2fma(spk, dyy, syy);
        const f2t oxy = f2fma(spk, sxy, sxy);

        // commit history: np -= dgam*n  <=>  np += cneg*d
        npxx = f2fma(cpk, dxx, npxx);
        npyy = f2fma(cpk, dyy, npyy);
        npzz = f2fma(cpk, dzz, npzz);
        npxy = f2fma(cpk, sxy, npxy);

        // fc2 partials (packed), then pair-sum + 8-lane shfl butterfly
        const f2t y0p = f2fma(w2p[0][0], oxx, f2fma(w2p[0][1], oyy, f2mul(w2p[0][2], oxy)));
        const f2t y1p = f2fma(w2p[1][0], oxx, f2fma(w2p[1][1], oyy, f2mul(w2p[1][2], oxy)));
        const f2t y2p = f2fma(w2p[2][0], oxx, f2fma(w2p[2][1], oyy, f2mul(w2p[2][2], oxy)));

        float y0l, y0h, y1l, y1h, y2l, y2h;
        f2unpack(y0p, y0l, y0h);
        f2unpack(y1p, y1l, y1h);
        f2unpack(y2p, y2l, y2h);
        float y0 = y0l + y0h;
        float y1 = y1l + y1h;
        float y2 = y2l + y2h;

#pragma unroll
        for (int off = 4; off >= 1; off >>= 1) {
            y0 += __shfl_xor_sync(0xffffffffu, y0, off);
            y1 += __shfl_xor_sync(0xffffffffu, y1, off);
            y2 += __shfl_xor_sync(0xffffffffu, y2, off);
        }

        if (leader) {
            ob[t * 3 + 0] = y0;
            ob[t * 3 + 1] = y1;
            ob[t * 3 + 2] = y2;
        }
    }
}

extern "C" void kernel_launch(void* const* d_in, const int* in_sizes, int n_in,
                              void* d_out, int out_size)
{
    const float* x  = (const float*)d_in[0];   // [B, 128, 3]
    const float* W1 = (const float*)d_in[1];   // [48, 3]
    const float* W2 = (const float*)d_in[2];   // [3, 48]
    float* out = (float*)d_out;                // [B, 128, 3]

    const int n_batch = in_sizes[0] / (T_STEPS * F_DIM);   // 16384
    const int n_threads_total = n_batch * (MATPTS / 2);    // 131072
    const int threads = 256;
    const int blocks = (n_threads_total + threads - 1) / threads;

    prnn_j2_kernel2<<<blocks, threads>>>(x, W1, W2, out, n_batch);
}

// round 5
// speedup vs baseline: 1.4535x; 1.0441x over previous
#include <cuda_runtime.h>
#include <math.h>

// J2 plane-strain elastoplasticity PRNN, fused full-sequence kernel, v3.
// 2 material points per thread via packed f32x2 (FFMA2); 8-lane shfl
// reduction; block=128 + launch_bounds(128,7) for single-wave occupancy;
// T unrolled by 4 with float4 x loads and float4 output stores.

namespace {
constexpr double E_MOD_D = 3130.0;
constexpr double NU_D    = 0.37;
constexpr double SIG_Y_D = 64.8;
constexpr double H_ISO_D = 300.0;
constexpr double MU_D    = E_MOD_D / (2.0 * (1.0 + NU_D));
constexpr double LAM_D   = E_MOD_D * NU_D / ((1.0 + NU_D) * (1.0 - 2.0 * NU_D));

constexpr int T_STEPS = 128;
constexpr int F_DIM   = 3;
constexpr int MATPTS  = 16;
constexpr int L_DIM   = MATPTS * F_DIM;   // 48
}

// ---- packed f32x2 helpers (sm_103a) ----
typedef unsigned long long f2t;

__device__ __forceinline__ f2t f2pack(float lo, float hi) {
    f2t r;
    asm("mov.b64 %0, {%1, %2};" : "=l"(r) : "f"(lo), "f"(hi));
    return r;
}
__device__ __forceinline__ void f2unpack(f2t a, float& lo, float& hi) {
    asm("mov.b64 {%0, %1}, %2;" : "=f"(lo), "=f"(hi) : "l"(a));
}
__device__ __forceinline__ f2t f2fma(f2t a, f2t b, f2t c) {
    f2t d;
    asm("fma.rn.f32x2 %0, %1, %2, %3;" : "=l"(d) : "l"(a), "l"(b), "l"(c));
    return d;
}
__device__ __forceinline__ f2t f2mul(f2t a, f2t b) {
    f2t d;
    asm("mul.rn.f32x2 %0, %1, %2;" : "=l"(d) : "l"(a), "l"(b));
    return d;
}
__device__ __forceinline__ f2t f2add(f2t a, f2t b) {
    f2t d;
    asm("add.rn.f32x2 %0, %1, %2;" : "=l"(d) : "l"(a), "l"(b));
    return d;
}

__global__ __launch_bounds__(128, 7)
void prnn_j2_kernel3(const float* __restrict__ x,
                     const float* __restrict__ W1,
                     const float* __restrict__ W2,
                     float* __restrict__ out,
                     int n_batch)
{
    const float MU    = (float)MU_D;
    const float LAM   = (float)LAM_D;
    const float SIG_Y = (float)SIG_Y_D;
    const float H_ISO = (float)H_ISO_D;
    const float INV_3MU_H = (float)(1.0 / (3.0 * MU_D + H_ISO_D));
    const float NEG15_INV = -1.5f * INV_3MU_H;
    const float TWO_MU = 2.0f * MU;

    const int tid = blockIdx.x * blockDim.x + threadIdx.x;
    const int b  = tid >> 3;         // batch element (8 threads per element)
    const int l8 = tid & 7;          // lane within 8-lane group
    if (b >= n_batch) return;

    const int m0 = l8;               // material point (lo half)
    const int m1 = l8 + 8;           // material point (hi half)

    // fc1 rows, packed across the two points; shear row pre-scaled by 0.5
    f2t w1p[3][3];
#pragma unroll
    for (int i = 0; i < 3; i++) {
        const float s = (i == 2) ? 0.5f : 1.0f;
#pragma unroll
        for (int j = 0; j < 3; j++)
            w1p[i][j] = f2pack(s * W1[(3 * m0 + i) * F_DIM + j],
                               s * W1[(3 * m1 + i) * F_DIM + j]);
    }

    // softplus(W2) entries for the two points, packed
    f2t w2p[3][3];
#pragma unroll
    for (int o = 0; o < 3; o++)
#pragma unroll
        for (int i = 0; i < 3; i++) {
            const float a = W2[o * L_DIM + 3 * m0 + i];
            const float c = W2[o * L_DIM + 3 * m1 + i];
            const float sa = fmaxf(a, 0.0f) + log1pf(expf(-fabsf(a)));
            const float sc = fmaxf(c, 0.0f) + log1pf(expf(-fabsf(c)));
            w2p[o][i] = f2pack(sa, sc);
        }

    // packed constants
    const f2t LAMp  = f2pack(LAM, LAM);
    const f2t TMUp  = f2pack(TWO_MU, TWO_MU);
    const f2t M13p  = f2pack(-1.0f / 3.0f, -1.0f / 3.0f);
    const f2t C15p  = f2pack(1.5f, 1.5f);
    const f2t ZEROp = f2pack(0.0f, 0.0f);

    // committed history: NEGATIVE plastic strain (packed) + alpha per half
    f2t npxx = ZEROp, npyy = ZEROp, npzz = ZEROp, npxy = ZEROp;
    float alpha0 = 0.0f, alpha1 = 0.0f;

    const float* xb = x   + (size_t)b * T_STEPS * 3;
    float*       ob = out + (size_t)b * T_STEPS * 3;
    const bool leader = (l8 == 0);

    for (int t4 = 0; t4 < T_STEPS; t4 += 4) {
        // 4 timesteps of strain path: 12 floats as 3x float4 (16B aligned)
        const float4 xv0 = *reinterpret_cast<const float4*>(xb + t4 * 3 + 0);
        const float4 xv1 = *reinterpret_cast<const float4*>(xb + t4 * 3 + 4);
        const float4 xv2 = *reinterpret_cast<const float4*>(xb + t4 * 3 + 8);
        const float xs[12] = {xv0.x, xv0.y, xv0.z, xv0.w,
                              xv1.x, xv1.y, xv1.z, xv1.w,
                              xv2.x, xv2.y, xv2.z, xv2.w};
        float ybuf[12];

#pragma unroll
        for (int u = 0; u < 4; u++) {
            const float xa  = xs[3 * u + 0];
            const float xbv = xs[3 * u + 1];
            const float xc  = xs[3 * u + 2];
            const f2t xp0 = f2pack(xa, xa);
            const f2t xp1 = f2pack(xbv, xbv);
            const f2t xp2 = f2pack(xc, xc);

            // elastic strain = fc1(x) + negative plastic strain
            const f2t ee_xx = f2fma(w1p[0][0], xp0, f2fma(w1p[0][1], xp1, f2fma(w1p[0][2], xp2, npxx)));
            const f2t ee_yy = f2fma(w1p[1][0], xp0, f2fma(w1p[1][1], xp1, f2fma(w1p[1][2], xp2, npyy)));
            const f2t ee_xy = f2fma(w1p[2][0], xp0, f2fma(w1p[2][1], xp1, f2fma(w1p[2][2], xp2, npxy)));
            const f2t ee_zz = npzz;

            // trial stress
            const f2t tr  = f2add(f2add(ee_xx, ee_yy), ee_zz);
            const f2t ltr = f2mul(LAMp, tr);
            const f2t sxx = f2fma(TMUp, ee_xx, ltr);
            const f2t syy = f2fma(TMUp, ee_yy, ltr);
            const f2t szz = f2fma(TMUp, ee_zz, ltr);
            const f2t sxy = f2mul(TMUp, ee_xy);

            // deviator via negative mean pressure
            const f2t pmn = f2mul(f2add(f2add(sxx, syy), szz), M13p);
            const f2t dxx = f2add(sxx, pmn);
            const f2t dyy = f2add(syy, pmn);
            const f2t dzz = f2add(szz, pmn);

            // q^2
            const f2t t2  = f2mul(sxy, sxy);
            const f2t q2p = f2mul(C15p,
                            f2fma(dxx, dxx, f2fma(dyy, dyy, f2fma(dzz, dzz, f2add(t2, t2)))));

            // scalar radial-return per half
            float q2a, q2b;
            f2unpack(q2p, q2a, q2b);

            const float rq0 = rsqrtf(fmaxf(q2a, 1e-24f));
            const float rq1 = rsqrtf(fmaxf(q2b, 1e-24f));
            const float qv0 = q2a * rq0;
            const float qv1 = q2b * rq1;
            const float f0 = qv0 - fmaf(H_ISO, alpha0, SIG_Y);
            const float f1 = qv1 - fmaf(H_ISO, alpha1, SIG_Y);
            const float g0 = fmaxf(f0, 0.0f);
            const float g1 = fmaxf(f1, 0.0f);
            alpha0 = fmaf(g0, INV_3MU_H, alpha0);
            alpha1 = fmaf(g1, INV_3MU_H, alpha1);
            const float cn0 = (g0 * NEG15_INV) * rq0;
            const float cn1 = (g1 * NEG15_INV) * rq1;

            const f2t cpk = f2pack(cn0, cn1);       // -dgam*1.5/q
            const f2t spk = f2mul(cpk, TMUp);       // -2*MU*dgam*1.5/q

            // corrected stress (radial return)
            const f2t oxx = f2fma(spk, dxx, sxx);
            const f2t oyy = f2fma(spk, dyy, syy);
            const f2t oxy = f2fma(spk, sxy, sxy);

            // commit history: np += cneg * d
            npxx = f2fma(cpk, dxx, npxx);
            npyy = f2fma(cpk, dyy, npyy);
            npzz = f2fma(cpk, dzz, npzz);
            npxy = f2fma(cpk, sxy, npxy);

            // fc2 partials (packed), pair-sum + 8-lane shfl butterfly
            const f2t y0p = f2fma(w2p[0][0], oxx, f2fma(w2p[0][1], oyy, f2mul(w2p[0][2], oxy)));
            const f2t y1p = f2fma(w2p[1][0], oxx, f2fma(w2p[1][1], oyy, f2mul(w2p[1][2], oxy)));
            const f2t y2p = f2fma(w2p[2][0], oxx, f2fma(w2p[2][1], oyy, f2mul(w2p[2][2], oxy)));

            float y0l, y0h, y1l, y1h, y2l, y2h;
            f2unpack(y0p, y0l, y0h);
            f2unpack(y1p, y1l, y1h);
            f2unpack(y2p, y2l, y2h);
            float y0 = y0l + y0h;
            float y1 = y1l + y1h;
            float y2 = y2l + y2h;

#pragma unroll
            for (int off = 4; off >= 1; off >>= 1) {
                y0 += __shfl_xor_sync(0xffffffffu, y0, off);
                y1 += __shfl_xor_sync(0xffffffffu, y1, off);
                y2 += __shfl_xor_sync(0xffffffffu, y2, off);
            }
            ybuf[3 * u + 0] = y0;
            ybuf[3 * u + 1] = y1;
            ybuf[3 * u + 2] = y2;
        }

        if (leader) {
            float4 o0 = make_float4(ybuf[0], ybuf[1], ybuf[2],  ybuf[3]);
            float4 o1 = make_float4(ybuf[4], ybuf[5], ybuf[6],  ybuf[7]);
            float4 o2 = make_float4(ybuf[8], ybuf[9], ybuf[10], ybuf[11]);
            *reinterpret_cast<float4*>(ob + t4 * 3 + 0) = o0;
            *reinterpret_cast<float4*>(ob + t4 * 3 + 4) = o1;
            *reinterpret_cast<float4*>(ob + t4 * 3 + 8) = o2;
        }
    }
}

extern "C" void kernel_launch(void* const* d_in, const int* in_sizes, int n_in,
                              void* d_out, int out_size)
{
    const float* x  = (const float*)d_in[0];   // [B, 128, 3]
    const float* W1 = (const float*)d_in[1];   // [48, 3]
    const float* W2 = (const float*)d_in[2];   // [3, 48]
    float* out = (float*)d_out;                // [B, 128, 3]

    const int n_batch = in_sizes[0] / (T_STEPS * F_DIM);   // 16384
    const int n_threads_total = n_batch * (MATPTS / 2);    // 131072
    const int threads = 128;
    const int blocks = (n_threads_total + threads - 1) / threads;  // 1024

    prnn_j2_kernel3<<<blocks, threads>>>(x, W1, W2, out, n_batch);
}

// round 6
// speedup vs baseline: 1.4899x; 1.0251x over previous
#include <cuda_runtime.h>
#include <math.h>

// J2 plane-strain elastoplasticity PRNN, fused full-sequence kernel, v4.
// 4 material points per thread = 2 independent f32x2 (FFMA2) pipelines
// (ILP-2 to hide the per-timestep dependency chain); 4-lane shfl
// reduction; block=64, launch_bounds(64,8) for balanced single wave.

namespace {
constexpr double E_MOD_D = 3130.0;
constexpr double NU_D    = 0.37;
constexpr double SIG_Y_D = 64.8;
constexpr double H_ISO_D = 300.0;
constexpr double MU_D    = E_MOD_D / (2.0 * (1.0 + NU_D));
constexpr double LAM_D   = E_MOD_D * NU_D / ((1.0 + NU_D) * (1.0 - 2.0 * NU_D));

constexpr int T_STEPS = 128;
constexpr int F_DIM   = 3;
constexpr int MATPTS  = 16;
constexpr int L_DIM   = MATPTS * F_DIM;   // 48
}

// ---- packed f32x2 helpers (sm_103a) ----
typedef unsigned long long f2t;

__device__ __forceinline__ f2t f2pack(float lo, float hi) {
    f2t r;
    asm("mov.b64 %0, {%1, %2};" : "=l"(r) : "f"(lo), "f"(hi));
    return r;
}
__device__ __forceinline__ void f2unpack(f2t a, float& lo, float& hi) {
    asm("mov.b64 {%0, %1}, %2;" : "=f"(lo), "=f"(hi) : "l"(a));
}
__device__ __forceinline__ f2t f2fma(f2t a, f2t b, f2t c) {
    f2t d;
    asm("fma.rn.f32x2 %0, %1, %2, %3;" : "=l"(d) : "l"(a), "l"(b), "l"(c));
    return d;
}
__device__ __forceinline__ f2t f2mul(f2t a, f2t b) {
    f2t d;
    asm("mul.rn.f32x2 %0, %1, %2;" : "=l"(d) : "l"(a), "l"(b));
    return d;
}
__device__ __forceinline__ f2t f2add(f2t a, f2t b) {
    f2t d;
    asm("add.rn.f32x2 %0, %1, %2;" : "=l"(d) : "l"(a), "l"(b));
    return d;
}

__global__ __launch_bounds__(64, 8)
void prnn_j2_kernel4(const float* __restrict__ x,
                     const float* __restrict__ W1,
                     const float* __restrict__ W2,
                     float* __restrict__ out,
                     int n_batch)
{
    const float SIG_Y = (float)SIG_Y_D;
    const float H_ISO = (float)H_ISO_D;
    const float INV_3MU_H = (float)(1.0 / (3.0 * MU_D + H_ISO_D));
    const float NEG15_INV = -1.5f * INV_3MU_H;
    const float LAM    = (float)LAM_D;
    const float TWO_MU = 2.0f * (float)MU_D;

    const int tid = blockIdx.x * blockDim.x + threadIdx.x;
    const int b  = tid >> 2;          // batch element (4 threads per element)
    const int l4 = tid & 3;           // lane within 4-lane group
    if (b >= n_batch) return;

    // 4 material points per thread, as 2 packed pairs:
    // pair 0: (l4, l4+4), pair 1: (l4+8, l4+12)
    int mm[4] = { l4, l4 + 4, l4 + 8, l4 + 12 };

    f2t w1p[2][3][3];
    f2t w2p[2][3][3];
#pragma unroll
    for (int p = 0; p < 2; p++) {
        const int m0 = mm[2 * p];
        const int m1 = mm[2 * p + 1];
#pragma unroll
        for (int i = 0; i < 3; i++) {
            const float s = (i == 2) ? 0.5f : 1.0f;
#pragma unroll
            for (int j = 0; j < 3; j++)
                w1p[p][i][j] = f2pack(s * W1[(3 * m0 + i) * F_DIM + j],
                                      s * W1[(3 * m1 + i) * F_DIM + j]);
        }
#pragma unroll
        for (int o = 0; o < 3; o++)
#pragma unroll
            for (int i = 0; i < 3; i++) {
                const float a = W2[o * L_DIM + 3 * m0 + i];
                const float c = W2[o * L_DIM + 3 * m1 + i];
                const float sa = fmaxf(a, 0.0f) + log1pf(expf(-fabsf(a)));
                const float sc = fmaxf(c, 0.0f) + log1pf(expf(-fabsf(c)));
                w2p[p][o][i] = f2pack(sa, sc);
            }
    }

    const f2t LAMp  = f2pack(LAM, LAM);
    const f2t TMUp  = f2pack(TWO_MU, TWO_MU);
    const f2t M13p  = f2pack(-1.0f / 3.0f, -1.0f / 3.0f);
    const f2t C15p  = f2pack(1.5f, 1.5f);
    const f2t ZEROp = f2pack(0.0f, 0.0f);

    // committed history: negative plastic strain per pair + alpha per point
    f2t np[2][4] = { {ZEROp, ZEROp, ZEROp, ZEROp},
                     {ZEROp, ZEROp, ZEROp, ZEROp} };
    float alpha[4] = {0.0f, 0.0f, 0.0f, 0.0f};

    const float* xb = x   + (size_t)b * T_STEPS * 3;
    float*       ob = out + (size_t)b * T_STEPS * 3;
    const bool leader = (l4 == 0);

    for (int t4 = 0; t4 < T_STEPS; t4 += 4) {
        const float4 xv0 = *reinterpret_cast<const float4*>(xb + t4 * 3 + 0);
        const float4 xv1 = *reinterpret_cast<const float4*>(xb + t4 * 3 + 4);
        const float4 xv2 = *reinterpret_cast<const float4*>(xb + t4 * 3 + 8);
        const float xs[12] = {xv0.x, xv0.y, xv0.z, xv0.w,
                              xv1.x, xv1.y, xv1.z, xv1.w,
                              xv2.x, xv2.y, xv2.z, xv2.w};
        float ybuf[12];

#pragma unroll
        for (int u = 0; u < 4; u++) {
            const float xa  = xs[3 * u + 0];
            const float xbv = xs[3 * u + 1];
            const float xc  = xs[3 * u + 2];
            const f2t xp0 = f2pack(xa, xa);
            const f2t xp1 = f2pack(xbv, xbv);
            const f2t xp2 = f2pack(xc, xc);

            f2t yacc0 = ZEROp, yacc1 = ZEROp, yacc2 = ZEROp;

#pragma unroll
            for (int p = 0; p < 2; p++) {
                // elastic strain = fc1(x) + negative plastic strain
                const f2t ee_xx = f2fma(w1p[p][0][0], xp0, f2fma(w1p[p][0][1], xp1, f2fma(w1p[p][0][2], xp2, np[p][0])));
                const f2t ee_yy = f2fma(w1p[p][1][0], xp0, f2fma(w1p[p][1][1], xp1, f2fma(w1p[p][1][2], xp2, np[p][1])));
                const f2t ee_xy = f2fma(w1p[p][2][0], xp0, f2fma(w1p[p][2][1], xp1, f2fma(w1p[p][2][2], xp2, np[p][3])));
                const f2t ee_zz = np[p][2];

                // trial stress
                const f2t tr  = f2add(f2add(ee_xx, ee_yy), ee_zz);
                const f2t ltr = f2mul(LAMp, tr);
                const f2t sxx = f2fma(TMUp, ee_xx, ltr);
                const f2t syy = f2fma(TMUp, ee_yy, ltr);
                const f2t szz = f2fma(TMUp, ee_zz, ltr);
                const f2t sxy = f2mul(TMUp, ee_xy);

                // deviator via negative mean pressure
                const f2t pmn = f2mul(f2add(f2add(sxx, syy), szz), M13p);
                const f2t dxx = f2add(sxx, pmn);
                const f2t dyy = f2add(syy, pmn);
                const f2t dzz = f2add(szz, pmn);

                // q^2
                const f2t t2  = f2mul(sxy, sxy);
                const f2t q2p = f2mul(C15p,
                                f2fma(dxx, dxx, f2fma(dyy, dyy, f2fma(dzz, dzz, f2add(t2, t2)))));

                // scalar radial-return for the two points of this pair
                float q2a, q2b;
                f2unpack(q2p, q2a, q2b);

                const float rq0 = rsqrtf(fmaxf(q2a, 1e-24f));
                const float rq1 = rsqrtf(fmaxf(q2b, 1e-24f));
                const float qv0 = q2a * rq0;
                const float qv1 = q2b * rq1;
                const float f0 = qv0 - fmaf(H_ISO, alpha[2 * p + 0], SIG_Y);
                const float f1 = qv1 - fmaf(H_ISO, alpha[2 * p + 1], SIG_Y);
                const float g0 = fmaxf(f0, 0.0f);
                const float g1 = fmaxf(f1, 0.0f);
                alpha[2 * p + 0] = fmaf(g0, INV_3MU_H, alpha[2 * p + 0]);
                alpha[2 * p + 1] = fmaf(g1, INV_3MU_H, alpha[2 * p + 1]);
                const float cn0 = (g0 * NEG15_INV) * rq0;
                const float cn1 = (g1 * NEG15_INV) * rq1;

                const f2t cpk = f2pack(cn0, cn1);       // -dgam*1.5/q
                const f2t spk = f2mul(cpk, TMUp);       // -2*MU*dgam*1.5/q

                // corrected stress (radial return)
                const f2t oxx = f2fma(spk, dxx, sxx);
                const f2t oyy = f2fma(spk, dyy, syy);
                const f2t oxy = f2fma(spk, sxy, sxy);

                // commit history: np += cneg * d
                np[p][0] = f2fma(cpk, dxx, np[p][0]);
                np[p][1] = f2fma(cpk, dyy, np[p][1]);
                np[p][2] = f2fma(cpk, dzz, np[p][2]);
                np[p][3] = f2fma(cpk, sxy, np[p][3]);

                // fc2 partials accumulated packed across pairs
                yacc0 = f2fma(w2p[p][0][0], oxx, f2fma(w2p[p][0][1], oyy, f2fma(w2p[p][0][2], oxy, yacc0)));
                yacc1 = f2fma(w2p[p][1][0], oxx, f2fma(w2p[p][1][1], oyy, f2fma(w2p[p][1][2], oxy, yacc1)));
                yacc2 = f2fma(w2p[p][2][0], oxx, f2fma(w2p[p][2][1], oyy, f2fma(w2p[p][2][2], oxy, yacc2)));
            }

            float y0l, y0h, y1l, y1h, y2l, y2h;
            f2unpack(yacc0, y0l, y0h);
            f2unpack(yacc1, y1l, y1h);
            f2unpack(yacc2, y2l, y2h);
            float y0 = y0l + y0h;
            float y1 = y1l + y1h;
            float y2 = y2l + y2h;

            // 4-lane butterfly (groups are lane-aligned: block % 4 == 0)
#pragma unroll
            for (int off = 2; off >= 1; off >>= 1) {
                y0 += __shfl_xor_sync(0xffffffffu, y0, off);
                y1 += __shfl_xor_sync(0xffffffffu, y1, off);
                y2 += __shfl_xor_sync(0xffffffffu, y2, off);
            }
            ybuf[3 * u + 0] = y0;
            ybuf[3 * u + 1] = y1;
            ybuf[3 * u + 2] = y2;
        }

        if (leader) {
            *reinterpret_cast<float4*>(ob + t4 * 3 + 0) =
                make_float4(ybuf[0], ybuf[1], ybuf[2],  ybuf[3]);
            *reinterpret_cast<float4*>(ob + t4 * 3 + 4) =
                make_float4(ybuf[4], ybuf[5], ybuf[6],  ybuf[7]);
            *reinterpret_cast<float4*>(ob + t4 * 3 + 8) =
                make_float4(ybuf[8], ybuf[9], ybuf[10], ybuf[11]);
        }
    }
}

extern "C" void kernel_launch(void* const* d_in, const int* in_sizes, int n_in,
                              void* d_out, int out_size)
{
    const float* x  = (const float*)d_in[0];   // [B, 128, 3]
    const float* W1 = (const float*)d_in[1];   // [48, 3]
    const float* W2 = (const float*)d_in[2];   // [3, 48]
    float* out = (float*)d_out;                // [B, 128, 3]

    const int n_batch = in_sizes[0] / (T_STEPS * F_DIM);   // 16384
    const int n_threads_total = n_batch * (MATPTS / 4);    // 65536
    const int threads = 64;
    const int blocks = (n_threads_total + threads - 1) / threads;  // 1024

    prnn_j2_kernel4<<<blocks, threads>>>(x, W1, W2, out, n_batch);
}

// round 10
// speedup vs baseline: 1.5244x; 1.0231x over previous
#include <cuda_runtime.h>
#include <math.h>

// J2 plane-strain elastoplasticity PRNN, fused full-sequence kernel, v5.
// 2 material points per thread (packed f32x2), block=128 (16 batch elems),
// double-buffered smem staging of x with cooperative prefetch one
// 4-timestep slab ahead; deviator-direct algebra (40 packed ops/pair).

namespace {
constexpr double E_MOD_D = 3130.0;
constexpr double NU_D    = 0.37;
constexpr double SIG_Y_D = 64.8;
constexpr double H_ISO_D = 300.0;
constexpr double MU_D    = E_MOD_D / (2.0 * (1.0 + NU_D));
constexpr double LAM_D   = E_MOD_D * NU_D / ((1.0 + NU_D) * (1.0 - 2.0 * NU_D));

constexpr int T_STEPS = 128;
constexpr int F_DIM   = 3;
constexpr int MATPTS  = 16;
constexpr int L_DIM   = MATPTS * F_DIM;   // 48
constexpr int GROUPS_PER_BLOCK = 16;      // batch elements per block
constexpr int ROW_F = 20;                 // padded smem row (floats), 80B stride
}

// ---- packed f32x2 helpers (sm_103a) ----
typedef unsigned long long f2t;

__device__ __forceinline__ f2t f2pack(float lo, float hi) {
    f2t r;
    asm("mov.b64 %0, {%1, %2};" : "=l"(r) : "f"(lo), "f"(hi));
    return r;
}
__device__ __forceinline__ void f2unpack(f2t a, float& lo, float& hi) {
    asm("mov.b64 {%0, %1}, %2;" : "=f"(lo), "=f"(hi) : "l"(a));
}
__device__ __forceinline__ f2t f2fma(f2t a, f2t b, f2t c) {
    f2t d;
    asm("fma.rn.f32x2 %0, %1, %2, %3;" : "=l"(d) : "l"(a), "l"(b), "l"(c));
    return d;
}
__device__ __forceinline__ f2t f2mul(f2t a, f2t b) {
    f2t d;
    asm("mul.rn.f32x2 %0, %1, %2;" : "=l"(d) : "l"(a), "l"(b));
    return d;
}
__device__ __forceinline__ f2t f2add(f2t a, f2t b) {
    f2t d;
    asm("add.rn.f32x2 %0, %1, %2;" : "=l"(d) : "l"(a), "l"(b));
    return d;
}

__global__ __launch_bounds__(128, 7)
void prnn_j2_kernel5(const float* __restrict__ x,
                     const float* __restrict__ W1,
                     const float* __restrict__ W2,
                     float* __restrict__ out,
                     int n_batch)
{
    const float SIG_Y = (float)SIG_Y_D;
    const float H_ISO = (float)H_ISO_D;
    const float INV_3MU_H = (float)(1.0 / (3.0 * MU_D + H_ISO_D));
    const float NEG15_INV = -1.5f * INV_3MU_H;
    const float TWO_MU = 2.0f * (float)MU_D;
    const float KM13   = -(float)(2.0 * MU_D / 3.0);          // -2MU/3
    const float KBULK  = (float)(LAM_D + 2.0 * MU_D / 3.0);   // bulk modulus

    // x staging: [2 bufs][16 groups][12 floats, padded to 20]
    __shared__ float xs[2][GROUPS_PER_BLOCK][ROW_F];

    const int li  = threadIdx.x;
    const int g   = li >> 3;               // group (batch elem) within block
    const int l8  = li & 7;                // lane within 8-lane group
    const int b   = blockIdx.x * GROUPS_PER_BLOCK + g;

    // loader role: threads 0..47 each own one 16B slice of the block's slab
    const int  lrow  = li / 3;             // group whose row we load
    const int  lpart = li % 3;             // which float4 of the 12 floats
    const bool isldr = (li < 48);
    const float* lsrc = x + (size_t)(blockIdx.x * GROUPS_PER_BLOCK + lrow) * (T_STEPS * 3)
                          + lpart * 4;

    const int m0 = l8;                     // material point (lo half)
    const int m1 = l8 + 8;                 // material point (hi half)

    // fc1 rows packed; shear row pre-scaled by 0.5
    f2t w1p[3][3];
#pragma unroll
    for (int i = 0; i < 3; i++) {
        const float s = (i == 2) ? 0.5f : 1.0f;
#pragma unroll
        for (int j = 0; j < 3; j++)
            w1p[i][j] = f2pack(s * W1[(3 * m0 + i) * F_DIM + j],
                               s * W1[(3 * m1 + i) * F_DIM + j]);
    }

    // softplus(W2) packed
    f2t w2p[3][3];
#pragma unroll
    for (int o = 0; o < 3; o++)
#pragma unroll
        for (int i = 0; i < 3; i++) {
            const float a = W2[o * L_DIM + 3 * m0 + i];
            const float c = W2[o * L_DIM + 3 * m1 + i];
            const float sa = fmaxf(a, 0.0f) + log1pf(expf(-fabsf(a)));
            const float sc = fmaxf(c, 0.0f) + log1pf(expf(-fabsf(c)));
            w2p[o][i] = f2pack(sa, sc);
        }

    const f2t TMUp  = f2pack(TWO_MU, TWO_MU);
    const f2t KM13p = f2pack(KM13, KM13);
    const f2t KBp   = f2pack(KBULK, KBULK);
    const f2t C15p  = f2pack(1.5f, 1.5f);
    const f2t ONEp  = f2pack(1.0f, 1.0f);
    const f2t ZEROp = f2pack(0.0f, 0.0f);

    // committed history: negative plastic strain + alpha per half
    f2t npxx = ZEROp, npyy = ZEROp, npzz = ZEROp, npxy = ZEROp;
    float alpha0 = 0.0f, alpha1 = 0.0f;

    float* ob = out + (size_t)b * T_STEPS * 3;
    const bool leader = (l8 == 0);

    // prologue: stage slab 0
    if (isldr) {
        const float4 v = __ldg(reinterpret_cast<const float4*>(lsrc));
        *reinterpret_cast<float4*>(&xs[0][lrow][lpart * 4]) = v;
    }
    __syncthreads();

    for (int it = 0; it < T_STEPS / 4; ++it) {
        const int t4 = it * 4;
        const int buf = it & 1;

        // prefetch next slab (clamped on last iter; redundant load harmless)
        float4 pv;
        const int tn = (it < T_STEPS / 4 - 1) ? (t4 + 4) : t4;
        if (isldr)
            pv = __ldg(reinterpret_cast<const float4*>(lsrc + tn * 3));

        // consume current slab from smem (broadcast, conflict-free)
        const float4 a0 = *reinterpret_cast<const float4*>(&xs[buf][g][0]);
        const float4 a1 = *reinterpret_cast<const float4*>(&xs[buf][g][4]);
        const float4 a2 = *reinterpret_cast<const float4*>(&xs[buf][g][8]);
        const float xv[12] = {a0.x, a0.y, a0.z, a0.w,
                              a1.x, a1.y, a1.z, a1.w,
                              a2.x, a2.y, a2.z, a2.w};
        float ybuf[12];

#pragma unroll
        for (int u = 0; u < 4; u++) {
            const float xa  = xv[3 * u + 0];
            const float xbv = xv[3 * u + 1];
            const float xc  = xv[3 * u + 2];
            const f2t xp0 = f2pack(xa, xa);
            const f2t xp1 = f2pack(xbv, xbv);
            const f2t xp2 = f2pack(xc, xc);

            // elastic strain = fc1(x) + negative plastic strain
            const f2t ee_xx = f2fma(w1p[0][0], xp0, f2fma(w1p[0][1], xp1, f2fma(w1p[0][2], xp2, npxx)));
            const f2t ee_yy = f2fma(w1p[1][0], xp0, f2fma(w1p[1][1], xp1, f2fma(w1p[1][2], xp2, npyy)));
            const f2t ee_xy = f2fma(w1p[2][0], xp0, f2fma(w1p[2][1], xp1, f2fma(w1p[2][2], xp2, npxy)));
            const f2t ee_zz = npzz;

            // deviatoric trial stress directly: d = 2MU*ee - (2MU/3)*tr * I
            const f2t tr  = f2add(f2add(ee_xx, ee_yy), ee_zz);
            const f2t cc  = f2mul(KM13p, tr);
            const f2t dxx = f2fma(TMUp, ee_xx, cc);
            const f2t dyy = f2fma(TMUp, ee_yy, cc);
            const f2t dzz = f2fma(TMUp, ee_zz, cc);
            const f2t sxy = f2mul(TMUp, ee_xy);
            const f2t pp  = f2mul(KBp, tr);        // mean stress

            // q^2 = 1.5*(dxx^2+dyy^2+dzz^2+2*sxy^2)
            const f2t t2  = f2mul(sxy, sxy);
            const f2t q2p = f2mul(C15p,
                            f2fma(dxx, dxx, f2fma(dyy, dyy, f2fma(dzz, dzz, f2add(t2, t2)))));

            // scalar radial-return per half
            float q2a, q2b;
            f2unpack(q2p, q2a, q2b);

            const float rq0 = rsqrtf(fmaxf(q2a, 1e-24f));
            const float rq1 = rsqrtf(fmaxf(q2b, 1e-24f));
            const float qv0 = q2a * rq0;
            const float qv1 = q2b * rq1;
            const float f0 = qv0 - fmaf(H_ISO, alpha0, SIG_Y);
            const float f1 = qv1 - fmaf(H_ISO, alpha1, SIG_Y);
            const float g0 = fmaxf(f0, 0.0f);
            const float g1 = fmaxf(f1, 0.0f);
            alpha0 = fmaf(g0, INV_3MU_H, alpha0);
            alpha1 = fmaf(g1, INV_3MU_H, alpha1);
            const float cn0 = (g0 * NEG15_INV) * rq0;
            const float cn1 = (g1 * NEG15_INV) * rq1;

            const f2t cpk = f2pack(cn0, cn1);            // -1.5*dgam/q
            const f2t w   = f2fma(cpk, TMUp, ONEp);      // 1 - 3*MU*dgam/q... scale on deviator

            // corrected stress: o = w*d + p*I (xx,yy); oxy = w*sxy
            const f2t oxx = f2fma(dxx, w, pp);
            const f2t oyy = f2fma(dyy, w, pp);
            const f2t oxy = f2mul(sxy, w);

            // commit history: np += cpk * d
            npxx = f2fma(cpk, dxx, npxx);
            npyy = f2fma(cpk, dyy, npyy);
            npzz = f2fma(cpk, dzz, npzz);
            npxy = f2fma(cpk, sxy, npxy);

            // fc2 partials (packed)
            const f2t y0p = f2fma(w2p[0][0], oxx, f2fma(w2p[0][1], oyy, f2mul(w2p[0][2], oxy)));
            const f2t y1p = f2fma(w2p[1][0], oxx, f2fma(w2p[1][1], oyy, f2mul(w2p[1][2], oxy)));
            const f2t y2p = f2fma(w2p[2][0], oxx, f2fma(w2p[2][1], oyy, f2mul(w2p[2][2], oxy)));

            float y0l, y0h, y1l, y1h, y2l, y2h;
            f2unpack(y0p, y0l, y0h);
            f2unpack(y1p, y1l, y1h);
            f2unpack(y2p, y2l, y2h);
            float y0 = y0l + y0h;
            float y1 = y1l + y1h;
            float y2 = y2l + y2h;

#pragma unroll
            for (int off = 4; off >= 1; off >>= 1) {
                y0 += __shfl_xor_sync(0xffffffffu, y0, off);
                y1 += __shfl_xor_sync(0xffffffffu, y1, off);
                y2 += __shfl_xor_sync(0xffffffffu, y2, off);
            }
            ybuf[3 * u + 0] = y0;
            ybuf[3 * u + 1] = y1;
            ybuf[3 * u + 2] = y2;
        }

        if (leader) {
            *reinterpret_cast<float4*>(ob + t4 * 3 + 0) =
                make_float4(ybuf[0], ybuf[1], ybuf[2],  ybuf[3]);
            *reinterpret_cast<float4*>(ob + t4 * 3 + 4) =
                make_float4(ybuf[4], ybuf[5], ybuf[6],  ybuf[7]);
            *reinterpret_cast<float4*>(ob + t4 * 3 + 8) =
                make_float4(ybuf[8], ybuf[9], ybuf[10], ybuf[11]);
        }

        // stage next slab into the other buffer, then block barrier
        if (isldr)
            *reinterpret_cast<float4*>(&xs[buf ^ 1][lrow][lpart * 4]) = pv;
        __syncthreads();
    }
}

extern "C" void kernel_launch(void* const* d_in, const int* in_sizes, int n_in,
                              void* d_out, int out_size)
{
    const float* x  = (const float*)d_in[0];   // [B, 128, 3]
    const float* W1 = (const float*)d_in[1];   // [48, 3]
    const float* W2 = (const float*)d_in[2];   // [3, 48]
    float* out = (float*)d_out;                // [B, 128, 3]

    const int n_batch = in_sizes[0] / (T_STEPS * F_DIM);   // 16384
    const int blocks = n_batch / GROUPS_PER_BLOCK;          // 1024
    prnn_j2_kernel5<<<blocks, 128>>>(x, W1, W2, out, n_batch);
}